// round 3
// baseline (speedup 1.0000x reference)
#include <cuda_runtime.h>
#include <cuda_bf16.h>

#define TILE_H 8
#define TILE_W 32
#define HALO_H (TILE_H + 2)   // 10
#define HALO_W (TILE_W + 2)   // 34
#define CCH    64
#define HH     128
#define WWD    128
#define NTAP   9
#define WSTRIDE 12            // 9 weights padded to 12 floats (48B) for aligned float4 loads

#define XS_ELEMS (CCH * HALO_H * HALO_W)     // 21760
#define WS_ELEMS (NTAP * CCH * WSTRIDE)      // 6912
#define SMEM_BYTES ((XS_ELEMS + WS_ELEMS) * 4)

extern __shared__ float smem[];

__global__ __launch_bounds__(256, 2)
void ahpf_fused_kernel(const float* __restrict__ x,
                       const float* __restrict__ Wt,
                       const float* __restrict__ bias,
                       float* __restrict__ out)
{
    float* xs = smem;                 // [c][halo_h][halo_w]
    float* ws = smem + XS_ELEMS;      // [tap][c][12] -> k contiguous

    const int tw0 = blockIdx.x * TILE_W;
    const int th0 = blockIdx.y * TILE_H;
    const int b   = blockIdx.z;
    const int tid = threadIdx.x;

    // Bias into registers (uniform LDG, latency hidden under staging)
    float bv[NTAP];
    #pragma unroll
    for (int k = 0; k < NTAP; ++k) bv[k] = bias[k];

    // --- Stage weights reordered: ws[(tap*C + c)*12 + k] = W[k][c][tap] ---
    for (int i = tid; i < NTAP * CCH * NTAP; i += 256) {
        int k   = i / (CCH * NTAP);
        int rem = i - k * (CCH * NTAP);
        int c   = rem / NTAP;
        int tap = rem - c * NTAP;
        ws[(tap * CCH + c) * WSTRIDE + k] = Wt[(k * CCH + c) * NTAP + tap];
    }

    // --- Stage x tile with zero halo (zero-pad semantics for the conv) ---
    const float* xb = x + (size_t)b * CCH * HH * WWD;
    for (int i = tid; i < XS_ELEMS; i += 256) {
        int c   = i / (HALO_H * HALO_W);
        int rem = i - c * (HALO_H * HALO_W);
        int r   = rem / HALO_W;
        int col = rem - r * HALO_W;
        int gh = th0 + r - 1;
        int gw = tw0 + col - 1;
        float v = 0.f;
        if (gh >= 0 && gh < HH && gw >= 0 && gw < WWD)
            v = xb[(c * HH + gh) * WWD + gw];
        xs[i] = v;
    }
    __syncthreads();

    const int w  = tid & (TILE_W - 1);
    const int h  = tid >> 5;
    const int gh = th0 + h;
    const int gw = tw0 + w;

    // ---------------- Conv: 9 logits per pixel ----------------
    float acc[NTAP];
    #pragma unroll
    for (int k = 0; k < NTAP; ++k) acc[k] = bv[k];

    for (int c = 0; c < CCH; ++c) {
        // halo coords of tap (di,dj) relative to pixel (h,w): row h+di, col w+dj
        const float* xr = xs + c * (HALO_H * HALO_W) + h * HALO_W + w;
        const float* wc = ws + c * WSTRIDE;
        #pragma unroll
        for (int di = 0; di < 3; ++di) {
            #pragma unroll
            for (int dj = 0; dj < 3; ++dj) {
                const float xv = xr[di * HALO_W + dj];
                const float* wq = wc + ((di * 3 + dj) * CCH) * WSTRIDE;
                const float4 w0 = *reinterpret_cast<const float4*>(wq);
                const float4 w1 = *reinterpret_cast<const float4*>(wq + 4);
                const float  w8 = wq[8];
                acc[0] = fmaf(xv, w0.x, acc[0]);
                acc[1] = fmaf(xv, w0.y, acc[1]);
                acc[2] = fmaf(xv, w0.z, acc[2]);
                acc[3] = fmaf(xv, w0.w, acc[3]);
                acc[4] = fmaf(xv, w1.x, acc[4]);
                acc[5] = fmaf(xv, w1.y, acc[5]);
                acc[6] = fmaf(xv, w1.z, acc[6]);
                acc[7] = fmaf(xv, w1.w, acc[7]);
                acc[8] = fmaf(xv, w8,   acc[8]);
            }
        }
    }

    // ---------------- softmax * hamming, renormalized ----------------
    // softmax denominator cancels: mask_k = e^{l_k - m} * ham_k / sum_j e^{l_j - m} * ham_j
    const float hamv[NTAP] = {0.0064f, 0.08f, 0.0064f,
                              0.08f,   1.0f,  0.08f,
                              0.0064f, 0.08f, 0.0064f};
    float mx = acc[0];
    #pragma unroll
    for (int k = 1; k < NTAP; ++k) mx = fmaxf(mx, acc[k]);
    float mask[NTAP];
    float msum = 0.f;
    #pragma unroll
    for (int k = 0; k < NTAP; ++k) {
        float e = __expf(acc[k] - mx) * hamv[k];
        mask[k] = e;
        msum += e;
    }
    const float inv = __fdividef(1.f, msum);
    #pragma unroll
    for (int k = 0; k < NTAP; ++k) mask[k] *= inv;

    // ---------------- precompute reflect-padded tap offsets (c-independent) ----
    int offs[NTAP];
    #pragma unroll
    for (int di = 0; di < 3; ++di) {
        int ghh = gh + di - 1;
        ghh = (ghh < 0) ? 1 : ((ghh >= HH) ? (HH - 2) : ghh);   // pad=1 reflect
        const int lh = ghh - th0 + 1;
        #pragma unroll
        for (int dj = 0; dj < 3; ++dj) {
            int gww = gw + dj - 1;
            gww = (gww < 0) ? 1 : ((gww >= WWD) ? (WWD - 2) : gww);
            const int lw = gww - tw0 + 1;
            offs[di * 3 + dj] = lh * HALO_W + lw;
        }
    }

    // ---------------- CARAFE lowpass + highpass residual ----------------
    float* outb = out + ((size_t)b * CCH) * HH * WWD + (size_t)gh * WWD + gw;
    for (int c = 0; c < CCH; ++c) {
        const float* xc = xs + c * (HALO_H * HALO_W);
        const float ctr = xc[(h + 1) * HALO_W + (w + 1)];
        float lp = mask[0] * xc[offs[0]];
        #pragma unroll
        for (int k = 1; k < NTAP; ++k) lp = fmaf(mask[k], xc[offs[k]], lp);
        outb[(size_t)c * HH * WWD] = 2.f * ctr - lp;
    }
}

extern "C" void kernel_launch(void* const* d_in, const int* in_sizes, int n_in,
                              void* d_out, int out_size)
{
    const float* x  = (const float*)d_in[0];
    const float* Wt = (const float*)d_in[1];
    const float* bs = (const float*)d_in[2];
    float* out = (float*)d_out;

    const int B = in_sizes[0] / (CCH * HH * WWD);

    cudaFuncSetAttribute(ahpf_fused_kernel,
                         cudaFuncAttributeMaxDynamicSharedMemorySize, SMEM_BYTES);

    dim3 grid(WWD / TILE_W, HH / TILE_H, B);
    ahpf_fused_kernel<<<grid, 256, SMEM_BYTES>>>(x, Wt, bs, out);
}

// round 4
// speedup vs baseline: 1.1343x; 1.1343x over previous
#include <cuda_runtime.h>
#include <cuda_bf16.h>

#define TILE_H 16
#define TILE_W 32
#define HALO_H (TILE_H + 2)   // 18
#define HALO_W (TILE_W + 2)   // 34
#define CCH    64
#define HH     128
#define WWD    128
#define NTAP   9
#define WSTRIDE 12            // 9 weights padded to 12 floats for aligned float4 loads
#define CHUNK  16
#define NCHUNK (CCH / CHUNK)  // 4

#define XS_ELEMS (CHUNK * HALO_H * HALO_W)   // 9792
#define WS_ELEMS (NTAP * CCH * WSTRIDE)      // 6912
#define SMEM_BYTES ((XS_ELEMS + WS_ELEMS) * 4)  // 66816 B -> 3 CTA/SM

extern __shared__ float smem[];

__device__ __forceinline__ void stage_chunk(float* __restrict__ xs,
                                            const float* __restrict__ xb,
                                            int cc0, int th0, int tw0, int tid)
{
    for (int i = tid; i < XS_ELEMS; i += 256) {
        int c   = i / (HALO_H * HALO_W);
        int rem = i - c * (HALO_H * HALO_W);
        int r   = rem / HALO_W;
        int col = rem - r * HALO_W;
        int gh = th0 + r - 1;
        int gw = tw0 + col - 1;
        float v = 0.f;
        if (gh >= 0 && gh < HH && gw >= 0 && gw < WWD)
            v = xb[((cc0 + c) * HH + gh) * WWD + gw];
        xs[i] = v;
    }
}

__global__ __launch_bounds__(256, 3)
void ahpf_fused_kernel(const float* __restrict__ x,
                       const float* __restrict__ Wt,
                       const float* __restrict__ bias,
                       float* __restrict__ out)
{
    float* xs = smem;                 // [CHUNK][18][34]
    float* ws = smem + XS_ELEMS;      // [tap][c][12], k contiguous

    const int tw0 = blockIdx.x * TILE_W;
    const int th0 = blockIdx.y * TILE_H;
    const int b   = blockIdx.z;
    const int tid = threadIdx.x;

    // --- Stage weights reordered: ws[(tap*64 + c)*12 + k] = W[k][c][tap] ---
    for (int i = tid; i < NTAP * CCH * NTAP; i += 256) {
        int k   = i / (CCH * NTAP);
        int rem = i - k * (CCH * NTAP);
        int c   = rem / NTAP;
        int tap = rem - c * NTAP;
        ws[(tap * CCH + c) * WSTRIDE + k] = Wt[(k * CCH + c) * NTAP + tap];
    }

    const float* xb = x + (size_t)b * CCH * HH * WWD;

    const int w   = tid & 31;        // 0..31
    const int h2  = tid >> 5;        // 0..7  -> pixel rows 2*h2, 2*h2+1
    const int gh0 = th0 + 2 * h2;
    const int gw  = tw0 + w;

    // ---------------- Conv: 9 logits for each of 2 stacked pixels ----------------
    float acc0[NTAP], acc1[NTAP];
    #pragma unroll
    for (int k = 0; k < NTAP; ++k) { float bk = bias[k]; acc0[k] = bk; acc1[k] = bk; }

    for (int ch = 0; ch < NCHUNK; ++ch) {
        stage_chunk(xs, xb, ch * CHUNK, th0, tw0, tid);
        __syncthreads();

        #pragma unroll 2
        for (int c = 0; c < CHUNK; ++c) {
            // union of the two pixels' 3x3 neighborhoods: 4 rows x 3 cols
            const float* xr = xs + c * (HALO_H * HALO_W) + (2 * h2) * HALO_W + w;
            float xv[4][3];
            #pragma unroll
            for (int r = 0; r < 4; ++r)
                #pragma unroll
                for (int j = 0; j < 3; ++j)
                    xv[r][j] = xr[r * HALO_W + j];

            const float* wc = ws + (ch * CHUNK + c) * WSTRIDE;
            #pragma unroll
            for (int di = 0; di < 3; ++di) {
                #pragma unroll
                for (int dj = 0; dj < 3; ++dj) {
                    const float* wq = wc + ((di * 3 + dj) * CCH) * WSTRIDE;
                    const float4 w0 = *reinterpret_cast<const float4*>(wq);
                    const float4 w1 = *reinterpret_cast<const float4*>(wq + 4);
                    const float  w8 = wq[8];
                    const float a0 = xv[di][dj];
                    const float a1 = xv[di + 1][dj];
                    acc0[0] = fmaf(a0, w0.x, acc0[0]);  acc1[0] = fmaf(a1, w0.x, acc1[0]);
                    acc0[1] = fmaf(a0, w0.y, acc0[1]);  acc1[1] = fmaf(a1, w0.y, acc1[1]);
                    acc0[2] = fmaf(a0, w0.z, acc0[2]);  acc1[2] = fmaf(a1, w0.z, acc1[2]);
                    acc0[3] = fmaf(a0, w0.w, acc0[3]);  acc1[3] = fmaf(a1, w0.w, acc1[3]);
                    acc0[4] = fmaf(a0, w1.x, acc0[4]);  acc1[4] = fmaf(a1, w1.x, acc1[4]);
                    acc0[5] = fmaf(a0, w1.y, acc0[5]);  acc1[5] = fmaf(a1, w1.y, acc1[5]);
                    acc0[6] = fmaf(a0, w1.z, acc0[6]);  acc1[6] = fmaf(a1, w1.z, acc1[6]);
                    acc0[7] = fmaf(a0, w1.w, acc0[7]);  acc1[7] = fmaf(a1, w1.w, acc1[7]);
                    acc0[8] = fmaf(a0, w8,   acc0[8]);  acc1[8] = fmaf(a1, w8,   acc1[8]);
                }
            }
        }
        __syncthreads();
    }

    // ---------------- softmax * hamming, renormalized (denominator cancels) -----
    const float hamv[NTAP] = {0.0064f, 0.08f, 0.0064f,
                              0.08f,   1.0f,  0.08f,
                              0.0064f, 0.08f, 0.0064f};
    float mask0[NTAP], mask1[NTAP];
    {
        float mx0 = acc0[0], mx1 = acc1[0];
        #pragma unroll
        for (int k = 1; k < NTAP; ++k) { mx0 = fmaxf(mx0, acc0[k]); mx1 = fmaxf(mx1, acc1[k]); }
        float s0 = 0.f, s1 = 0.f;
        #pragma unroll
        for (int k = 0; k < NTAP; ++k) {
            float e0 = __expf(acc0[k] - mx0) * hamv[k];
            float e1 = __expf(acc1[k] - mx1) * hamv[k];
            mask0[k] = e0; mask1[k] = e1;
            s0 += e0; s1 += e1;
        }
        const float i0 = __fdividef(1.f, s0);
        const float i1 = __fdividef(1.f, s1);
        #pragma unroll
        for (int k = 0; k < NTAP; ++k) { mask0[k] *= i0; mask1[k] *= i1; }
    }

    // ---------------- reflect-padded offsets (shared by the pixel pair) ---------
    int roff[4], coff[3];
    #pragma unroll
    for (int i = 0; i < 4; ++i) {
        int g = gh0 - 1 + i;
        g = (g < 0) ? 1 : ((g >= HH) ? (HH - 2) : g);
        roff[i] = (g - th0 + 1) * HALO_W;
    }
    #pragma unroll
    for (int j = 0; j < 3; ++j) {
        int g = gw - 1 + j;
        g = (g < 0) ? 1 : ((g >= WWD) ? (WWD - 2) : g);
        coff[j] = g - tw0 + 1;
    }

    // ---------------- CARAFE lowpass + highpass residual (restaged chunks) ------
    float* outb = out + ((size_t)b * CCH) * HH * WWD + (size_t)gh0 * WWD + gw;

    for (int ch = 0; ch < NCHUNK; ++ch) {
        stage_chunk(xs, xb, ch * CHUNK, th0, tw0, tid);
        __syncthreads();

        #pragma unroll 2
        for (int c = 0; c < CHUNK; ++c) {
            const float* xc = xs + c * (HALO_H * HALO_W);
            float v[4][3];
            #pragma unroll
            for (int i = 0; i < 4; ++i)
                #pragma unroll
                for (int j = 0; j < 3; ++j)
                    v[i][j] = xc[roff[i] + coff[j]];

            // v[1][1] = center of pixel0, v[2][1] = center of pixel1 (never reflected)
            float lp0 = mask0[0] * v[0][0];
            float lp1 = mask1[0] * v[1][0];
            #pragma unroll
            for (int di = 0; di < 3; ++di)
                #pragma unroll
                for (int dj = 0; dj < 3; ++dj) {
                    if (di == 0 && dj == 0) continue;
                    lp0 = fmaf(mask0[di * 3 + dj], v[di][dj],     lp0);
                    lp1 = fmaf(mask1[di * 3 + dj], v[di + 1][dj], lp1);
                }

            const size_t co = (size_t)(ch * CHUNK + c) * HH * WWD;
            outb[co]       = 2.f * v[1][1] - lp0;
            outb[co + WWD] = 2.f * v[2][1] - lp1;
        }
        __syncthreads();
    }
}

extern "C" void kernel_launch(void* const* d_in, const int* in_sizes, int n_in,
                              void* d_out, int out_size)
{
    const float* x  = (const float*)d_in[0];
    const float* Wt = (const float*)d_in[1];
    const float* bs = (const float*)d_in[2];
    float* out = (float*)d_out;

    const int B = in_sizes[0] / (CCH * HH * WWD);

    cudaFuncSetAttribute(ahpf_fused_kernel,
                         cudaFuncAttributeMaxDynamicSharedMemorySize, SMEM_BYTES);

    dim3 grid(WWD / TILE_W, HH / TILE_H, B);
    ahpf_fused_kernel<<<grid, 256, SMEM_BYTES>>>(x, Wt, bs, out);
}